// round 8
// baseline (speedup 1.0000x reference)
#include <cuda_runtime.h>
#include <math.h>

#define B_  32
#define T_  1024
#define C_  128
#define G_  896
#define G3_ 2688
#define H_  896
#define NB  112      // persistent CTAs for the scan (1/SM guaranteed by smem)

typedef unsigned long long u64;

// ---------------- device scratch (allocation-free: __device__ globals) -------
__device__ __align__(256) float g_gx [(size_t)T_ * G3_ * B_];  // [T][3G][B]
__device__ __align__(256) float g_hs2[(size_t)T_ * G_  * B_];  // [t/2][G][B][2]
__device__ __align__(256) float g_h  [2 * G_ * B_];            // double-buffered h, [G][B]
__device__ unsigned g_bar_count = 0;
__device__ volatile unsigned g_bar_gen = 0;

// ---------------- helpers ----------------------------------------------------
__device__ __forceinline__ void fma2(u64 &acc, u64 a, u64 b) {
    asm("fma.rn.f32x2 %0, %1, %2, %0;" : "+l"(acc) : "l"(a), "l"(b));
}
__device__ __forceinline__ u64 pack2(float x, float y) {
    u64 r; asm("mov.b64 %0, {%1,%2};" : "=l"(r) : "f"(x), "f"(y)); return r;
}
__device__ __forceinline__ float2 unpack2(u64 v) {
    float2 r; asm("mov.b64 {%0,%1}, %2;" : "=f"(r.x), "=f"(r.y) : "l"(v)); return r;
}
__device__ __forceinline__ float sigm(float x) {
    return __fdividef(1.0f, 1.0f + __expf(-x));
}
__device__ __forceinline__ float tanh_fast(float x) {
    float e = __expf(2.0f * x);
    return 1.0f - __fdividef(2.0f, e + 1.0f);
}
__device__ __forceinline__ void cp_async16(float* smem_dst, const float* gsrc) {
    unsigned s = (unsigned)__cvta_generic_to_shared(smem_dst);
    asm volatile("cp.async.cg.shared.global [%0], [%1], 16;" :: "r"(s), "l"(gsrc));
}
#define CP_COMMIT() asm volatile("cp.async.commit_group;")
#define CP_WAIT(n)  asm volatile("cp.async.wait_group %0;" :: "n"(n))

// ============================================================================
__global__ void k_nop() {}

// ============================================================================
// gx[t][row][b] = b_ih[row] + sum_c x[b][t][c] * w_ih[row][c]
// ============================================================================
__global__ __launch_bounds__(128) void k_gx(const float* __restrict__ x,
                                            const float* __restrict__ state,
                                            const float* __restrict__ w_ih,
                                            const float* __restrict__ b_ih) {
    __shared__ float ws[128 * 64];   // [c][r]
    __shared__ float xs[128 * 32];   // [c][b]
    const int tid = threadIdx.x;
    const int r0  = blockIdx.x * 64;
    const int t   = blockIdx.y;

    if (blockIdx.x == 0 && blockIdx.y == 0) {
        for (int i = tid; i < G_ * B_; i += 128) {
            int g = i >> 5, b = i & 31;
            g_h[g * 32 + b] = state[b * G_ + g];
        }
    }

    for (int i = tid; i < 64 * 32; i += 128) {
        int r = i >> 5, cq = (i & 31) * 4;
        float4 v = *(const float4*)(w_ih + (size_t)(r0 + r) * C_ + cq);
        ws[(cq+0)*64 + r] = v.x; ws[(cq+1)*64 + r] = v.y;
        ws[(cq+2)*64 + r] = v.z; ws[(cq+3)*64 + r] = v.w;
    }
    for (int i = tid; i < 32 * 32; i += 128) {
        int b = i >> 5, cq = (i & 31) * 4;
        float4 v = *(const float4*)(x + ((size_t)b * T_ + t) * C_ + cq);
        xs[(cq+0)*32 + b] = v.x; xs[(cq+1)*32 + b] = v.y;
        xs[(cq+2)*32 + b] = v.z; xs[(cq+3)*32 + b] = v.w;
    }
    __syncthreads();

    const int rt  = tid >> 3;
    const int bpt = tid & 7;
    const int rr  = rt * 4;
    const int bb  = bpt * 4;
    u64 acc[4][2] = {};

#pragma unroll 2
    for (int k = 0; k < 128; ++k) {
        const float* wk = ws + k * 64 + rr;
        u64 h0 = *(const u64*)(xs + k * 32 + bb);
        u64 h1 = *(const u64*)(xs + k * 32 + bb + 2);
#pragma unroll
        for (int i = 0; i < 4; ++i) {
            u64 wp = pack2(wk[i], wk[i]);
            fma2(acc[i][0], wp, h0);
            fma2(acc[i][1], wp, h1);
        }
    }
#pragma unroll
    for (int i = 0; i < 4; ++i) {
        float bias = b_ih[r0 + rr + i];
        float* op = g_gx + ((size_t)t * G3_ + r0 + rr + i) * B_ + bb;
        float2 a0 = unpack2(acc[i][0]); a0.x += bias; a0.y += bias;
        float2 a1 = unpack2(acc[i][1]); a1.x += bias; a1.y += bias;
        *(float2*)(op)     = a0;
        *(float2*)(op + 2) = a1;
    }
}

// ============================================================================
// Persistent GRU scan, 112 CTAs x 512 threads (16 warps, 4/SMSP).
// Warp w owns k-slice [w*56, w*56+56): cp.asyncs its own h slice (2 groups of
// 28 rows, compute overlaps copy). Lane = (jl 0..7, bq 0..3): 1 j x 8 b x 3
// gates, b-pairs in the f32x2 lanes. Partials go to a reduction buffer that
// ALIASES hs (hs is dead post-mainloop; hold is register-prefetched), guarded
// by a syncthreads. Epilogue on threads 0..255 (j = warp, b = lane).
// SMEM: hs 114688 + ws 86016 = 200704 B -> 1 CTA/SM, 112 co-resident.
// ============================================================================
#define RNN_SMEM ((G_*B_ + 896*24) * 4)   // 200704

__global__ __launch_bounds__(512) void k_rnn(const float* __restrict__ w_hh,
                                             const float* __restrict__ b_hh) {
    extern __shared__ float sm[];
    float* hs   = sm;                         // [896][32]
    float* ws   = sm + G_ * B_;               // [896][24]  ws[k][g*8+j]
    u64*   redp = (u64*)sm;                   // ALIASES hs: [16 w][3 g][8 j][17 u64 pad]
    float* redf = (float*)sm;                 // same as floats (row stride 34)

    const int tid  = threadIdx.x;
    const int warp = tid >> 5;
    const int lane = tid & 31;
    const int cta  = blockIdx.x;
    const int j0   = cta * 8;
    const int k0   = warp * 56;

    // one-time: ws[k][g*8+j] = w_hh[g*G + j0+j][k]
    for (int row = 0; row < 24; ++row) {
        const float* src = w_hh + ((size_t)(row >> 3) * G_ + j0 + (row & 7)) * G_;
        for (int k = tid; k < G_; k += 512) ws[k * 24 + row] = src[k];
    }
    __syncthreads();

    // mainloop coords
    const int jl = lane >> 2;        // 0..7
    const int bq = lane & 3;         // 0..3 -> b0 = bq*8
    const int b0 = bq * 8;

    // epilogue coords (threads 0..255): thread = (j = warp, b = lane)
    const int je  = j0 + (warp & 7);
    float bhr = 0.f, bhz = 0.f, bhn = 0.f;
    if (tid < 256) {
        bhr = b_hh[je];
        bhz = b_hh[G_  + je];
        bhn = b_hh[2*G_ + je];
    }

    for (int t = 0; t < T_; ++t) {
        const int cur = t & 1, nxt = cur ^ 1;
        const float* hg = g_h + cur * (G_ * B_);

        // epilogue prefetch (hidden under h-copy + mainloop)
        float pgr = 0.f, pgz = 0.f, pgn = 0.f, phold = 0.f;
        if (tid < 256) {
            const float* gxp = g_gx + (size_t)t * G3_ * B_ + lane;
            pgr   = __ldcs(gxp + (size_t)je * B_);
            pgz   = __ldcs(gxp + (size_t)(G_ + je) * B_);
            pgn   = __ldcs(gxp + (size_t)(2 * G_ + je) * B_);
            phold = __ldcg(hg + je * 32 + lane);
        }

        // warp-private h slice: 56 rows via cp.async.cg, 2 groups of 28 rows
        {
            const float* src = hg + k0 * 32;
            float* dst = hs + k0 * 32;
#pragma unroll
            for (int i = 0; i < 7; ++i)
                cp_async16(dst + (i * 32 + lane) * 4, src + (i * 32 + lane) * 4);
            CP_COMMIT();
#pragma unroll
            for (int i = 7; i < 14; ++i)
                cp_async16(dst + (i * 32 + lane) * 4, src + (i * 32 + lane) * 4);
            CP_COMMIT();
        }

        u64 ar[4] = {}, az[4] = {}, an[4] = {};

        CP_WAIT(1);          // group A (rows k0..k0+27) ready
        __syncwarp();
        {
            const float* wp = ws + (size_t)k0 * 24 + jl;
            const u64*   hp = (const u64*)(hs + (size_t)k0 * 32 + b0);
#pragma unroll 4
            for (int k = 0; k < 28; ++k) {
                float wr = wp[0], wz = wp[8], wn = wp[16];
                u64 h0 = hp[0], h1 = hp[1], h2 = hp[2], h3 = hp[3];
                u64 wrd = pack2(wr, wr), wzd = pack2(wz, wz), wnd = pack2(wn, wn);
                fma2(ar[0], wrd, h0); fma2(ar[1], wrd, h1);
                fma2(ar[2], wrd, h2); fma2(ar[3], wrd, h3);
                fma2(az[0], wzd, h0); fma2(az[1], wzd, h1);
                fma2(az[2], wzd, h2); fma2(az[3], wzd, h3);
                fma2(an[0], wnd, h0); fma2(an[1], wnd, h1);
                fma2(an[2], wnd, h2); fma2(an[3], wnd, h3);
                wp += 24; hp += 16;
            }
        }
        CP_WAIT(0);          // group B ready
        __syncwarp();
        {
            const float* wp = ws + (size_t)(k0 + 28) * 24 + jl;
            const u64*   hp = (const u64*)(hs + (size_t)(k0 + 28) * 32 + b0);
#pragma unroll 4
            for (int k = 0; k < 28; ++k) {
                float wr = wp[0], wz = wp[8], wn = wp[16];
                u64 h0 = hp[0], h1 = hp[1], h2 = hp[2], h3 = hp[3];
                u64 wrd = pack2(wr, wr), wzd = pack2(wz, wz), wnd = pack2(wn, wn);
                fma2(ar[0], wrd, h0); fma2(ar[1], wrd, h1);
                fma2(ar[2], wrd, h2); fma2(ar[3], wrd, h3);
                fma2(az[0], wzd, h0); fma2(az[1], wzd, h1);
                fma2(az[2], wzd, h2); fma2(az[3], wzd, h3);
                fma2(an[0], wnd, h0); fma2(an[1], wnd, h1);
                fma2(an[2], wnd, h2); fma2(an[3], wnd, h3);
                wp += 24; hp += 16;
            }
        }

        // all warps done reading hs before partials overwrite it (red aliases hs)
        __syncthreads();

        // partials -> red[w][g][jl] rows of 17 u64 (pad kills STS conflicts)
        {
            u64* rp = redp + ((size_t)(warp * 3 * 8) + jl) * 17 + bq * 4;
#pragma unroll
            for (int i = 0; i < 4; ++i) rp[i]            = ar[i];
#pragma unroll
            for (int i = 0; i < 4; ++i) rp[8 * 17 + i]   = az[i];
#pragma unroll
            for (int i = 0; i < 4; ++i) rp[16 * 17 + i]  = an[i];
        }
        __syncthreads();

        // epilogue: thread (j = warp&7, b = lane) for tid < 256
        if (tid < 256) {
            float sr = 0.f, sz = 0.f, sn = 0.f;
            const int jrow = warp & 7;
#pragma unroll
            for (int w = 0; w < 16; ++w) {
                const float* rf = redf + ((size_t)(w * 3 * 8) + jrow) * 34 + lane;
                sr += rf[0];
                sz += rf[8 * 34];
                sn += rf[16 * 34];
            }
            float r = sigm(pgr + sr + bhr);
            float z = sigm(pgz + sz + bhz);
            float n = tanh_fast(pgn + r * (sn + bhn));
            float h = (1.0f - z) * n + z * phold;

            g_h[nxt * (G_ * B_) + je * 32 + lane] = h;
            g_hs2[(size_t)(t >> 1) * G_ * 64 + (size_t)je * 64 + lane * 2 + (t & 1)] = h;
            __threadfence();    // every writer: h visible before barrier arrival
        }

        // sense-reversing grid barrier (self-restoring -> replay-safe)
        __syncthreads();
        if (tid == 0) {
            unsigned old = g_bar_gen;
            if (atomicAdd(&g_bar_count, 1u) == NB - 1) {
                g_bar_count = 0;
                __threadfence();
                g_bar_gen = old + 1;
            } else {
                while (g_bar_gen == old) { __nanosleep(32); }
            }
            __threadfence();
        }
        __syncthreads();
    }
}

// ============================================================================
// out[b][t][h] = relu(sum_g hs[t][g][b] * w_post[h][g] + b_post[h])
// t-pairs in f32x2 lanes. grid (14 h-tiles, 512 t-pairs), 128 threads.
// ============================================================================
__global__ __launch_bounds__(128) void k_post(const float* __restrict__ w_post,
                                              const float* __restrict__ b_post,
                                              float* __restrict__ out) {
    __shared__ float wt [64 * 64];   // [k][h]
    __shared__ float ht2[64 * 64];   // [k][b*2]
    const int tid = threadIdx.x;
    const int hb  = blockIdx.x * 64;
    const int tp  = blockIdx.y;
    const int ht  = tid >> 3;
    const int bt  = tid & 7;
    const int hh  = ht * 4;
    const int b0  = bt * 4;

    u64 acc[4][4];
#pragma unroll
    for (int i = 0; i < 4; ++i)
#pragma unroll
        for (int j = 0; j < 4; ++j) acc[i][j] = 0ull;

    for (int ch = 0; ch < 14; ++ch) {
        const int g0 = ch * 64;
        for (int i = tid; i < 64 * 16; i += 128) {
            int r = i >> 4, cq = (i & 15) * 4;
            float4 v = *(const float4*)(w_post + (size_t)(hb + r) * G_ + g0 + cq);
            wt[(cq+0)*64 + r] = v.x; wt[(cq+1)*64 + r] = v.y;
            wt[(cq+2)*64 + r] = v.z; wt[(cq+3)*64 + r] = v.w;
        }
        const float* src = g_hs2 + ((size_t)tp * G_ + g0) * 64;
        for (int i = tid * 4; i < 4096; i += 512)
            *(float4*)(ht2 + i) = *(const float4*)(src + i);
        __syncthreads();

#pragma unroll 4
        for (int k = 0; k < 64; ++k) {
            float4 w4 = *(const float4*)(wt + k * 64 + hh);
            u64 wd0 = pack2(w4.x, w4.x), wd1 = pack2(w4.y, w4.y);
            u64 wd2 = pack2(w4.z, w4.z), wd3 = pack2(w4.w, w4.w);
            const u64* hp = (const u64*)(ht2 + k * 64 + b0 * 2);
            u64 h0 = hp[0], h1 = hp[1], h2 = hp[2], h3 = hp[3];
            fma2(acc[0][0], wd0, h0); fma2(acc[0][1], wd0, h1);
            fma2(acc[0][2], wd0, h2); fma2(acc[0][3], wd0, h3);
            fma2(acc[1][0], wd1, h0); fma2(acc[1][1], wd1, h1);
            fma2(acc[1][2], wd1, h2); fma2(acc[1][3], wd1, h3);
            fma2(acc[2][0], wd2, h0); fma2(acc[2][1], wd2, h1);
            fma2(acc[2][2], wd2, h2); fma2(acc[2][3], wd2, h3);
            fma2(acc[3][0], wd3, h0); fma2(acc[3][1], wd3, h1);
            fma2(acc[3][2], wd3, h2); fma2(acc[3][3], wd3, h3);
        }
        __syncthreads();
    }

    const int t0 = tp * 2, t1 = t0 + 1;
    float bi0 = b_post[hb + hh + 0], bi1 = b_post[hb + hh + 1];
    float bi2 = b_post[hb + hh + 2], bi3 = b_post[hb + hh + 3];
#pragma unroll
    for (int j = 0; j < 4; ++j) {
        int b = b0 + j;
        float2 a0 = unpack2(acc[0][j]), a1 = unpack2(acc[1][j]);
        float2 a2 = unpack2(acc[2][j]), a3 = unpack2(acc[3][j]);
        float4 o0 = make_float4(fmaxf(a0.x + bi0, 0.f), fmaxf(a1.x + bi1, 0.f),
                                fmaxf(a2.x + bi2, 0.f), fmaxf(a3.x + bi3, 0.f));
        float4 o1 = make_float4(fmaxf(a0.y + bi0, 0.f), fmaxf(a1.y + bi1, 0.f),
                                fmaxf(a2.y + bi2, 0.f), fmaxf(a3.y + bi3, 0.f));
        *(float4*)(out + ((size_t)b * T_ + t0) * H_ + hb + hh) = o0;
        *(float4*)(out + ((size_t)b * T_ + t1) * H_ + hb + hh) = o1;
    }
}

// ============================================================================
__global__ void k_last(float* __restrict__ out) {
    int i = blockIdx.x * blockDim.x + threadIdx.x;
    if (i < G_ * B_) {
        int b = i / G_, g = i % G_;
        out[(size_t)B_ * T_ * H_ + i] = g_h[g * 32 + b];
    }
}

// ============================================================================
extern "C" void kernel_launch(void* const* d_in, const int* in_sizes, int n_in,
                              void* d_out, int out_size) {
    const float* x      = (const float*)d_in[0];
    const float* state  = (const float*)d_in[1];
    const float* w_ih   = (const float*)d_in[2];
    const float* w_hh   = (const float*)d_in[3];
    const float* b_ih   = (const float*)d_in[4];
    const float* b_hh   = (const float*)d_in[5];
    const float* w_post = (const float*)d_in[6];
    const float* b_post = (const float*)d_in[7];
    float* out = (float*)d_out;

    static int smem_set = 0;
    if (!smem_set) {
        cudaFuncSetAttribute(k_rnn, cudaFuncAttributeMaxDynamicSharedMemorySize, RNN_SMEM);
        smem_set = 1;
    }

    // k_rnn is the 4th launch: ncu captures launch #4.
    k_gx  <<<dim3(42, 1024), 128>>>(x, state, w_ih, b_ih);
    k_nop <<<1, 32>>>();
    k_nop <<<1, 32>>>();
    k_rnn <<<NB, 512, RNN_SMEM>>>(w_hh, b_hh);
    k_post<<<dim3(14, 512), 128>>>(w_post, b_post, out);
    k_last<<<112, 256>>>(out);
}